// round 5
// baseline (speedup 1.0000x reference)
#include <cuda_runtime.h>

#define NWIRES 11
#define NLAY   4
#define NGATES 88
#define PIX    1024
#define NB     1024

// Per gate: (c1,d1,c2,d2) = (u00.re, u00.im, u01.re, u01.im); SU(2): u10=(-c2,d2), u11=(c1,-d1)
__device__ float4 g_G[NGATES];

__global__ void precompute_gates(const float* __restrict__ w0,
                                 const float* __restrict__ w1) {
    int idx = blockIdx.x * blockDim.x + threadIdx.x;
    if (idx >= NGATES) return;
    const float PI_F = 3.14159265358979323846f;
    int k = idx / 44, rem = idx % 44;
    const float* w = (k == 0) ? w0 : w1;
    float phi   = PI_F * tanhf(w[rem * 3 + 0]);
    float theta = PI_F * tanhf(w[rem * 3 + 1]);
    float omega = PI_F * tanhf(w[rem * 3 + 2]);
    float c = cosf(0.5f * theta), s = sinf(0.5f * theta);
    float apo = 0.5f * (phi + omega), bpo = 0.5f * (phi - omega);
    float are = cosf(apo), aim = -sinf(apo);   // a = exp(-i*apo)
    float bre = cosf(bpo), bim = sinf(bpo);    // b = exp(+i*bpo)
    g_G[idx] = make_float4(are * c, aim * c, -bre * s, -bim * s);
}

// inverse CNOT-chain permutation (gather form)
__device__ __forceinline__ int cinv_idx(int dst, int r) {
    int src = dst;
    for (int q = NWIRES - 1; q >= 0; q--) {
        int cb = NWIRES - 1 - q;
        int tq = q + r; if (tq >= NWIRES) tq -= NWIRES;
        int tbit = NWIRES - 1 - tq;
        src ^= ((src >> cb) & 1) << tbit;
    }
    return src;
}
// amp index s -> float offset of its re part in the float4-pair smem layout
__device__ __forceinline__ int fmap(int s) { return ((s >> 1) << 2) | (s & 1); }

// SU(2) gate on an inter-register bit. flip negates (d1, c2) for XOR-relabeled slot order.
__device__ __forceinline__ void gate_reg(float2 aE[8], float2 aO[8],
                                         float4 g, int stride, bool flip) {
    const float c1 = g.x, d1 = flip ? -g.y : g.y, c2 = flip ? -g.z : g.z, d2 = g.w;
    #pragma unroll
    for (int j0 = 0; j0 < 8; j0++) {
        if (j0 & stride) continue;
        const int j1 = j0 | stride;
        {
            float2 a0 = aE[j0], a1 = aE[j1];
            aE[j0].x = c1*a0.x - d1*a0.y + c2*a1.x - d2*a1.y;
            aE[j0].y = c1*a0.y + d1*a0.x + c2*a1.y + d2*a1.x;
            aE[j1].x = -c2*a0.x - d2*a0.y + c1*a1.x + d1*a1.y;
            aE[j1].y = -c2*a0.y + d2*a0.x + c1*a1.y - d1*a1.x;
        }
        {
            float2 a0 = aO[j0], a1 = aO[j1];
            aO[j0].x = c1*a0.x - d1*a0.y + c2*a1.x - d2*a1.y;
            aO[j0].y = c1*a0.y + d1*a0.x + c2*a1.y + d2*a1.x;
            aO[j1].x = -c2*a0.x - d2*a0.y + c1*a1.x + d1*a1.y;
            aO[j1].y = -c2*a0.y + d2*a0.x + c1*a1.y - d1*a1.x;
        }
    }
}

// SU(2) gate on thread lane bit 0 (amp bit 1 in layout 3); partner via shfl.
__device__ __forceinline__ void gate_shfl(float2 aE[8], float2 aO[8], float4 g, int hi) {
    const float csx = g.x;
    const float csy = hi ? -g.y : g.y;
    const float cox = hi ? -g.z : g.z;
    const float coy = g.w;
    #pragma unroll
    for (int j = 0; j < 8; j++) {
        float pex = __shfl_xor_sync(0xffffffffu, aE[j].x, 1);
        float pey = __shfl_xor_sync(0xffffffffu, aE[j].y, 1);
        float pox = __shfl_xor_sync(0xffffffffu, aO[j].x, 1);
        float poy = __shfl_xor_sync(0xffffffffu, aO[j].y, 1);
        float ex = aE[j].x, ey = aE[j].y, ox = aO[j].x, oy = aO[j].y;
        aE[j].x = csx*ex - csy*ey + cox*pex - coy*pey;
        aE[j].y = csx*ey + csy*ex + cox*pey + coy*pex;
        aO[j].x = csx*ox - csy*oy + cox*pox - coy*poy;
        aO[j].y = csx*oy + csy*ox + cox*poy + coy*pox;
    }
}

// SU(2) gate on the pack bit (amp bit 0): mixes aE/aO within the thread.
__device__ __forceinline__ void gate_intra(float2 aE[8], float2 aO[8], float4 g) {
    const float c1 = g.x, d1 = g.y, c2 = g.z, d2 = g.w;
    #pragma unroll
    for (int j = 0; j < 8; j++) {
        float ex = aE[j].x, ey = aE[j].y, ox = aO[j].x, oy = aO[j].y;
        aE[j].x = c1*ex - d1*ey + c2*ox - d2*oy;
        aE[j].y = c1*ey + d1*ex + c2*oy + d2*ox;
        aO[j].x = -c2*ex - d2*ey + c1*ox + d1*oy;
        aO[j].y = -c2*ey + d2*ex + c1*oy - d1*ox;
    }
}

__global__ __launch_bounds__(128, 8)
void qsim_kernel(const float* __restrict__ x,
                 const float* __restrict__ y,
                 float* __restrict__ out) {
    __shared__ float4 sp4[1024];   // pair P: (re0,re1,im0,im1)  -- 16 KB
    __shared__ int fT[4][128];
    __shared__ int fR[4][8];
    __shared__ int fW[4];
    __shared__ float red[4];
    float* smf = (float*)sp4;

    const int b = blockIdx.x, t = threadIdx.x;
    const float* xb = x + (size_t)b * PIX;

    // ---- permutation tables (address-space, XOR-composable) ----
    for (int i2 = t; i2 < 512; i2 += 128) {
        int rr = i2 >> 7, tt = i2 & 127;
        fT[rr][tt] = fmap(cinv_idx(tt << 1, rr + 1));
    }
    if (t < 32) fR[t >> 3][t & 7] = fmap(cinv_idx((t & 7) << 8, (t >> 3) + 1));
    if (t < 4)  fW[t] = fmap(cinv_idx(1, t + 1));

    // ---- norm ----
    float ss = 0.0f;
    #pragma unroll
    for (int i = t; i < PIX; i += 128) { float v = xb[i]; ss += v * v; }
    #pragma unroll
    for (int o = 16; o > 0; o >>= 1) ss += __shfl_xor_sync(0xffffffffu, ss, o);
    if ((t & 31) == 0) red[t >> 5] = ss;
    __syncthreads();
    float inv = 1.0f / sqrtf(red[0] + red[1] + red[2] + red[3]);

    // ---- embedding: pair P = (emb[P], 0 | 0, 0) ----
    #pragma unroll
    for (int s8 = 0; s8 < 8; s8++) {
        int P = t + (s8 << 7);
        sp4[P] = make_float4(xb[P] * inv, 0.0f, 0.0f, 0.0f);
    }
    const float yhalf = 0.5f * y[b];
    const float yc = cosf(yhalf), ys = sinf(yhalf);
    __syncthreads();

    float2 aE[8], aO[8];
    const int t31 = (t >> 1) & 7;
    const int B3x = ((t >> 1) << 4) | (t31 << 1) | (t & 1);
    const int b2  = ((t >> 4) << 7) | (t & 15);

    #pragma unroll 1
    for (int k = 0; k < 2; k++) {
        #pragma unroll 1
        for (int l = 0; l < NLAY; l++) {
            const int gbase = k * 44 + l * 11;
            const int pend = (k == 0 && l == 0) ? 0 : ((l == 0) ? 4 : l);

            // ===== layout 1: reg bits = i[10:8] (wires 0,1,2); perm folded into gather =====
            if (pend == 0) {
                #pragma unroll
                for (int r = 0; r < 8; r++) {
                    float4 v = sp4[(r << 7) | t];
                    aE[r] = make_float2(v.x, v.z);
                    aO[r] = make_float2(v.y, v.w);
                }
            } else {
                const int base = fT[pend - 1][t], wv = fW[pend - 1];
                #pragma unroll
                for (int r = 0; r < 8; r++) {
                    int A0 = base ^ fR[pend - 1][r];
                    int A1 = A0 ^ wv;
                    aE[r] = make_float2(smf[A0], smf[A0 + 2]);
                    aO[r] = make_float2(smf[A1], smf[A1 + 2]);
                }
            }
            gate_reg(aE, aO, g_G[gbase + 0], 4, false);
            gate_reg(aE, aO, g_G[gbase + 1], 2, false);
            gate_reg(aE, aO, g_G[gbase + 2], 1, false);
            // RACE FIX: the permuted gather above reads scattered addresses while
            // the store below writes linear ones. All reads must complete block-wide
            // before any write. The gates are register-only, so this barrier sits
            // after them and hides behind the FFMA chain.
            __syncthreads();
            #pragma unroll
            for (int r = 0; r < 8; r++)
                sp4[(r << 7) | t] = make_float4(aE[r].x, aO[r].x, aE[r].y, aO[r].y);
            __syncthreads();

            // ===== layout 2: reg bits = i[7:5] (wires 3,4,5); per-thread in-place safe =====
            #pragma unroll
            for (int r = 0; r < 8; r++) {
                float4 v = sp4[b2 | (r << 4)];
                aE[r] = make_float2(v.x, v.z);
                aO[r] = make_float2(v.y, v.w);
            }
            gate_reg(aE, aO, g_G[gbase + 3], 4, false);
            gate_reg(aE, aO, g_G[gbase + 4], 2, false);
            gate_reg(aE, aO, g_G[gbase + 5], 1, false);
            #pragma unroll
            for (int r = 0; r < 8; r++)
                sp4[b2 | (r << 4)] = make_float4(aE[r].x, aO[r].x, aE[r].y, aO[r].y);
            __syncthreads();

            // ===== layout 3: reg bits = i[4:2] (wires 6,7,8) XOR-relabeled; bit1 shfl; bit0 intra;
            //       per-thread in-place safe =====
            #pragma unroll
            for (int u = 0; u < 8; u++) {
                float4 v = sp4[B3x ^ (u << 1)];
                aE[u] = make_float2(v.x, v.z);
                aO[u] = make_float2(v.y, v.w);
            }
            gate_reg(aE, aO, g_G[gbase + 6], 4, (t31 >> 2) & 1);
            gate_reg(aE, aO, g_G[gbase + 7], 2, (t31 >> 1) & 1);
            gate_reg(aE, aO, g_G[gbase + 8], 1, t31 & 1);
            gate_shfl(aE, aO, g_G[gbase + 9], t & 1);
            {
                float4 G = g_G[gbase + 10];
                if (l == 0) {   // fuse RX(y): F = Rot * RX
                    float c1 = G.x, d1 = G.y, c2 = G.z, d2 = G.w;
                    G = make_float4(c1 * yc + d2 * ys, d1 * yc - c2 * ys,
                                    d1 * ys + c2 * yc, -c1 * ys + d2 * yc);
                }
                gate_intra(aE, aO, G);
            }
            #pragma unroll
            for (int u = 0; u < 8; u++)
                sp4[B3x ^ (u << 1)] = make_float4(aE[u].x, aO[u].x, aE[u].y, aO[u].y);
            __syncthreads();
        }
    }

    // ---- epilogue: final perm (r=4) folded; probs of even basis states ----
    float* ob = out + (size_t)b * PIX;
    const int baseo = fT[3][t];
    #pragma unroll
    for (int s8 = 0; s8 < 8; s8++) {
        int addr = baseo ^ fR[3][s8];
        float re = smf[addr], im = smf[addr + 2];
        float pr = (re * re + im * im) * 1024.0f;
        ob[(s8 << 7) + t] = fminf(pr, 1.0f);
    }
}

extern "C" void kernel_launch(void* const* d_in, const int* in_sizes, int n_in,
                              void* d_out, int out_size) {
    const float* x  = (const float*)d_in[0];
    const float* y  = (const float*)d_in[1];
    const float* w0 = (const float*)d_in[2];
    const float* w1 = (const float*)d_in[3];
    float* out = (float*)d_out;

    precompute_gates<<<1, 128>>>(w0, w1);
    qsim_kernel<<<NB, 128>>>(x, y, out);
}